// round 11
// baseline (speedup 1.0000x reference)
#include <cuda_runtime.h>
#include <cstdint>
#include <math.h>

// Problem constants
#define Bb   2
#define Ss   2048
#define Dd   512
#define Hh   8
#define DHh  64
#define DFFf 2048
#define Mrows (Bb * Ss)   // 4096

// ---------------- scratch (no allocation allowed) ----------------
__device__ float g_q[Mrows * Dd];
__device__ float g_k[Mrows * Dd];
__device__ float g_v[Mrows * Dd];
__device__ float g_ctx[Mrows * Dd];
__device__ float g_attn[Mrows * Dd];
__device__ float g_h[Mrows * Dd];
__device__ float g_ff1[(size_t)Mrows * DFFf];
__device__ float g_ff2[Mrows * Dd];

// =========================== helpers ====================================
__device__ __forceinline__ void mma1688(float* c, const uint32_t* a, const uint32_t* b) {
    asm volatile(
        "mma.sync.aligned.m16n8k8.row.col.f32.tf32.tf32.f32 "
        "{%0,%1,%2,%3}, {%4,%5,%6,%7}, {%8,%9}, {%0,%1,%2,%3};"
        : "+f"(c[0]), "+f"(c[1]), "+f"(c[2]), "+f"(c[3])
        : "r"(a[0]), "r"(a[1]), "r"(a[2]), "r"(a[3]),
          "r"(b[0]), "r"(b[1]));
}

// ---------------------------------------------------------------------------
// tf32 mma.sync GEMM body: C[m,n] = sum_k A[m,k]*W[n,k] + bias[n]
// CTA tile 128x128x32, 256 thr = 8 warps (4x2), warp tile 32x64.
// Double-buffered frag-layout smem; FULL register prefetch (A+B LDGs batched
// before the compute phase, staged after) for max MLP / latency hiding.
// ---------------------------------------------------------------------------
template <bool RELU>
__device__ __forceinline__ void gemm_body(
    const float* __restrict__ A, const float* __restrict__ W,
    const float* __restrict__ bias, float* __restrict__ C,
    int N, int K)
{
    extern __shared__ uint32_t smg[];
    uint32_t* sAb[2] = { smg,        smg + 4096 };
    uint32_t* sBb[2] = { smg + 8192, smg + 12288 };

    const int tid  = threadIdx.x;
    const int wid  = tid >> 5;
    const int lane = tid & 31;
    const int wrow = wid >> 1;
    const int wcol = wid & 1;
    const int m0   = blockIdx.y * 128;
    const int n0   = blockIdx.x * 128;
    const int g    = lane >> 2;
    const int t    = lane & 3;

    float acc[2][8][4];
#pragma unroll
    for (int i = 0; i < 2; i++)
#pragma unroll
        for (int j = 0; j < 8; j++)
#pragma unroll
            for (int e = 0; e < 4; e++) acc[i][j][e] = 0.f;

    auto loadA = [&](float4* p, int k0) {
#pragma unroll
        for (int it = 0; it < 4; ++it) {
            const int f = tid + 256 * it;
            const int r = f >> 3, c4 = f & 7;
            p[it] = *(const float4*)(A + (size_t)(m0 + r) * K + k0 + c4 * 4);
        }
    };
    auto loadB = [&](float4* p, int k0) {
#pragma unroll
        for (int it = 0; it < 4; ++it) {
            const int f = tid + 256 * it;
            const int r = f >> 3, c4 = f & 7;
            p[it] = *(const float4*)(W + (size_t)(n0 + r) * K + k0 + c4 * 4);
        }
    };
    auto stageA = [&](uint32_t* buf, const float4* p) {
#pragma unroll
        for (int it = 0; it < 4; ++it) {
            const int f = tid + 256 * it;
            const int r = f >> 3, c4 = f & 7;
            const int mt = r >> 4, rr = r & 15;
            const int ga = rr & 7, rh = rr >> 3;
            const int ks = c4 >> 1, ch = c4 & 1;
            const int reg = rh + 2 * ch;
            uint32_t* dst = buf + (((mt * 4 + ks) * 32) + ga * 4) * 4 + reg;
            dst[0 * 4] = __float_as_uint(p[it].x);
            dst[1 * 4] = __float_as_uint(p[it].y);
            dst[2 * 4] = __float_as_uint(p[it].z);
            dst[3 * 4] = __float_as_uint(p[it].w);
        }
    };
    auto stageB = [&](uint32_t* buf, const float4* p) {
#pragma unroll
        for (int it = 0; it < 4; ++it) {
            const int f = tid + 256 * it;
            const int r = f >> 3, c4 = f & 7;
            const int nt = r >> 3, gb = r & 7;
            const int ks = c4 >> 1, reg = c4 & 1;
            uint32_t* dst = buf + (((nt * 4 + ks) * 32) + gb * 4) * 2 + reg;
            dst[0 * 2] = __float_as_uint(p[it].x);
            dst[1 * 2] = __float_as_uint(p[it].y);
            dst[2 * 2] = __float_as_uint(p[it].z);
            dst[3 * 2] = __float_as_uint(p[it].w);
        }
    };
    auto compute4 = [&](const uint32_t* bufA, const uint32_t* bufB) {
#pragma unroll
        for (int ks = 0; ks < 4; ++ks) {
            uint32_t afr[2][4];
#pragma unroll
            for (int mt = 0; mt < 2; ++mt) {
                const uint4 va = *(const uint4*)
                    (bufA + (((wrow * 2 + mt) * 4 + ks) * 32 + lane) * 4);
                afr[mt][0] = va.x; afr[mt][1] = va.y;
                afr[mt][2] = va.z; afr[mt][3] = va.w;
            }
            uint32_t bfr[8][2];
#pragma unroll
            for (int nt = 0; nt < 8; ++nt) {
                const uint2 vb = *(const uint2*)
                    (bufB + (((wcol * 8 + nt) * 4 + ks) * 32 + lane) * 2);
                bfr[nt][0] = vb.x; bfr[nt][1] = vb.y;
            }
#pragma unroll
            for (int mt = 0; mt < 2; ++mt)
#pragma unroll
                for (int nt = 0; nt < 8; ++nt)
                    mma1688(acc[mt][nt], afr[mt], bfr[nt]);
        }
    };

    // ---- prologue: stage chunk 0 into buffer 0 ----
    float4 pa[4], pb[4];
    loadA(pa, 0); loadB(pb, 0);
    stageA(sAb[0], pa); stageB(sBb[0], pb);
    __syncthreads();

    const int nc = K >> 5;
    for (int c = 0; c < nc; ++c) {
        const int nb = c & 1, fb = nb ^ 1;
        const bool nxt = (c + 1 < nc);
        if (nxt) {                      // all 8 LDG.128 in flight before compute
            loadA(pa, (c + 1) << 5);
            loadB(pb, (c + 1) << 5);
        }
        compute4(sAb[nb], sBb[nb]);     // 64 HMMA hide the LDG latency
        if (nxt) {
            stageA(sAb[fb], pa);
            stageB(sBb[fb], pb);
        }
        __syncthreads();
    }

    // ---- epilogue ----
#pragma unroll
    for (int mt = 0; mt < 2; ++mt) {
        const int rbase = m0 + wrow * 32 + mt * 16;
#pragma unroll
        for (int nt = 0; nt < 8; ++nt) {
            const int cbase = n0 + wcol * 64 + nt * 8 + t * 2;
            const float b0 = bias[cbase];
            const float b1 = bias[cbase + 1];
            float2 o0, o1;
            o0.x = acc[mt][nt][0] + b0;  o0.y = acc[mt][nt][1] + b1;
            o1.x = acc[mt][nt][2] + b0;  o1.y = acc[mt][nt][3] + b1;
            if (RELU) {
                o0.x = fmaxf(o0.x, 0.f); o0.y = fmaxf(o0.y, 0.f);
                o1.x = fmaxf(o1.x, 0.f); o1.y = fmaxf(o1.y, 0.f);
            }
            *(float2*)(C + (size_t)(rbase + g)     * N + cbase) = o0;
            *(float2*)(C + (size_t)(rbase + g + 8) * N + cbase) = o1;
        }
    }
}

template <bool RELU>
__global__ void __launch_bounds__(256)
tc_gemm_kernel(const float* __restrict__ A, const float* __restrict__ W,
               const float* __restrict__ bias, float* __restrict__ C,
               int N, int K)
{
    gemm_body<RELU>(A, W, bias, C, N, K);
}

// Merged QKV: grid.z selects {Wq,Wk,Wv}.
__global__ void __launch_bounds__(256)
qkv_kernel(const float* __restrict__ x,
           const float* __restrict__ Wq, const float* __restrict__ bq,
           const float* __restrict__ Wk, const float* __restrict__ bk,
           const float* __restrict__ Wv, const float* __restrict__ bv,
           float* __restrict__ q, float* __restrict__ k, float* __restrict__ v)
{
    const float* W; const float* bias; float* C;
    if (blockIdx.z == 0)      { W = Wq; bias = bq; C = q; }
    else if (blockIdx.z == 1) { W = Wk; bias = bk; C = k; }
    else                      { W = Wv; bias = bv; C = v; }
    gemm_body<false>(x, W, bias, C, Dd, Dd);
}

// ---------------------------------------------------------------------------
// Tensor-core causal flash attention (tf32 mma.sync) with K/V register
// prefetch: next tile's 16 LDG.128 issue right after the staging barrier and
// complete under the current tile's 128 HMMA + softmax.
// grid = (S/64, B*H), 128 threads = 4 warps; warp owns 16 q rows.
// Heavy tiles first (qt = gridDim.x-1 - blockIdx.x).
// ---------------------------------------------------------------------------
__global__ void __launch_bounds__(128) attn_kernel(
    const float* __restrict__ q, const float* __restrict__ k,
    const float* __restrict__ v, const float* __restrict__ alphas,
    float* __restrict__ ctx)
{
    extern __shared__ uint32_t smu[];
    uint32_t* Qf  = smu;
    uint32_t* Kf  = smu + 4096;
    uint32_t* Vf  = smu + 8192;
    float*    Psm = (float*)(smu + 12288);

    const int qt = (gridDim.x - 1) - blockIdx.x;   // heavy first
    const int bh = blockIdx.y;
    const int b  = bh >> 3;
    const int h  = bh & 7;

    const size_t base = (size_t)b * Ss * Dd + (size_t)h * DHh;
    const float* qb = q + base;
    const float* kb = k + base;
    const float* vb = v + base;
    float* cb = ctx + base;

    const int tid  = threadIdx.x;
    const int wid  = tid >> 5;
    const int lane = tid & 31;
    const int g    = lane >> 2;
    const int t    = lane & 3;

    auto loadKV = [&](float4* kr, float4* vr, int kt) {
#pragma unroll
        for (int it = 0; it < 8; ++it) {
            const int f = tid + 128 * it;
            const int r = f >> 4, c4 = f & 15;
            const size_t goff = (size_t)(kt * 64 + r) * Dd + c4 * 4;
            kr[it] = *(const float4*)(kb + goff);
            vr[it] = *(const float4*)(vb + goff);
        }
    };
    auto stageKV = [&](const float4* kr, const float4* vr) {
#pragma unroll
        for (int it = 0; it < 8; ++it) {
            const int f = tid + 128 * it;
            const int r = f >> 4, c4 = f & 15;
            {   // K: n-role = kpos (r), k-role = dim
                const int gg = r & 7, nt = r >> 3, kc = c4 >> 1, reg = c4 & 1;
                uint32_t* dst = &Kf[((kc * 8 + nt) * 32 + gg * 4) * 2 + reg];
                dst[0] = __float_as_uint(kr[it].x); dst[2] = __float_as_uint(kr[it].y);
                dst[4] = __float_as_uint(kr[it].z); dst[6] = __float_as_uint(kr[it].w);
            }
            {   // V: k-role = kpos (r), n-role = dim
                const int kc = r >> 3, tt = r & 7;
                const int tq = tt & 3, reg = tt >> 2;
                const int nt = c4 >> 1, gb = (c4 & 1) * 4;
                uint32_t* dst = &Vf[((kc * 8 + nt) * 32 + gb * 4 + tq) * 2 + reg];
                dst[0]  = __float_as_uint(vr[it].x); dst[8]  = __float_as_uint(vr[it].y);
                dst[16] = __float_as_uint(vr[it].z); dst[24] = __float_as_uint(vr[it].w);
            }
        }
    };

    // ---- stage Q tile (64x64) into a-frag layout; prefetch KV tile 0 ----
    float4 kr[8], vr[8];
    loadKV(kr, vr, 0);
#pragma unroll
    for (int it = 0; it < 8; ++it) {
        const int f  = tid + 128 * it;
        const int r  = f >> 4;
        const int c4 = f & 15;
        const float4 v4 = *(const float4*)(qb + (size_t)(qt * 64 + r) * Dd + c4 * 4);
        const int w   = r >> 4;
        const int rr  = r & 15;
        const int gg  = rr & 7;
        const int rh  = rr >> 3;
        const int kc  = c4 >> 1;
        const int reg = rh + 2 * (c4 & 1);
        uint32_t* dst = &Qf[(((w * 8 + kc) * 32) + gg * 4) * 4 + reg];
        dst[0 * 4] = __float_as_uint(v4.x);
        dst[1 * 4] = __float_as_uint(v4.y);
        dst[2 * 4] = __float_as_uint(v4.z);
        dst[3 * 4] = __float_as_uint(v4.w);
    }

    float oacc[8][4];
#pragma unroll
    for (int nt = 0; nt < 8; ++nt)
#pragma unroll
        for (int e = 0; e < 4; ++e) oacc[nt][e] = 0.f;
    float m0 = -1e30f, m1 = -1e30f, l0 = 0.f, l1 = 0.f;

    const int rloc0 = wid * 16 + g;
    const int nkt   = qt + 1;
    const float* Pw = Psm + wid * 1088;
    float* PwW      = Psm + wid * 1088;

    for (int kt = 0; kt < nkt; ++kt) {
        stageKV(kr, vr);     // regs -> smem (current tile)
        __syncthreads();     // staging visible; prior compute done

        if (kt + 1 < nkt)
            loadKV(kr, vr, kt + 1);   // LDGs for next tile, hidden by compute

        // ---- S = Q @ K^T ----
        float sacc[8][4];
#pragma unroll
        for (int nt = 0; nt < 8; ++nt)
#pragma unroll
            for (int e = 0; e < 4; ++e) sacc[nt][e] = 0.f;
#pragma unroll
        for (int kc = 0; kc < 8; ++kc) {
            const uint4 aq4 = *(const uint4*)&Qf[((wid * 8 + kc) * 32 + lane) * 4];
            uint32_t aq[4] = {aq4.x, aq4.y, aq4.z, aq4.w};
#pragma unroll
            for (int nt = 0; nt < 8; ++nt) {
                const uint2 kb2 = *(const uint2*)&Kf[((kc * 8 + nt) * 32 + lane) * 2];
                uint32_t bf[2] = {kb2.x, kb2.y};
                mma1688(sacc[nt], aq, bf);
            }
        }

        // ---- softmax (register/shuffle only) ----
        const bool diag = (kt == qt);
        const float scale = 0.125f;
        float rm0 = -1e30f, rm1 = -1e30f;
#pragma unroll
        for (int nt = 0; nt < 8; ++nt) {
            const int jc = nt * 8 + 2 * t;
            float s0 = sacc[nt][0] * scale;
            float s1 = sacc[nt][1] * scale;
            float s2 = sacc[nt][2] * scale;
            float s3 = sacc[nt][3] * scale;
            if (diag) {
                if (jc     > rloc0)     s0 = -1e30f;
                if (jc + 1 > rloc0)     s1 = -1e30f;
                if (jc     > rloc0 + 8) s2 = -1e30f;
                if (jc + 1 > rloc0 + 8) s3 = -1e30f;
            }
            sacc[nt][0] = s0; sacc[nt][1] = s1;
            sacc[nt][2] = s2; sacc[nt][3] = s3;
            rm0 = fmaxf(rm0, fmaxf(s0, s1));
            rm1 = fmaxf(rm1, fmaxf(s2, s3));
        }
        rm0 = fmaxf(rm0, __shfl_xor_sync(0xffffffffu, rm0, 1));
        rm0 = fmaxf(rm0, __shfl_xor_sync(0xffffffffu, rm0, 2));
        rm1 = fmaxf(rm1, __shfl_xor_sync(0xffffffffu, rm1, 1));
        rm1 = fmaxf(rm1, __shfl_xor_sync(0xffffffffu, rm1, 2));

        const float mn0 = fmaxf(m0, rm0);
        const float mn1 = fmaxf(m1, rm1);
        const float al0 = __expf(m0 - mn0);
        const float al1 = __expf(m1 - mn1);
        float sum0 = 0.f, sum1 = 0.f;
#pragma unroll
        for (int nt = 0; nt < 8; ++nt) {
            const int jc = nt * 8 + 2 * t;
            const float p0 = __expf(sacc[nt][0] - mn0);
            const float p1 = __expf(sacc[nt][1] - mn0);
            const float p2 = __expf(sacc[nt][2] - mn1);
            const float p3 = __expf(sacc[nt][3] - mn1);
            sum0 += p0 + p1;
            sum1 += p2 + p3;
            *(float2*)(PwW + g * 68 + jc)       = make_float2(p0, p1);
            *(float2*)(PwW + (g + 8) * 68 + jc) = make_float2(p2, p3);
        }
        sum0 += __shfl_xor_sync(0xffffffffu, sum0, 1);
        sum0 += __shfl_xor_sync(0xffffffffu, sum0, 2);
        sum1 += __shfl_xor_sync(0xffffffffu, sum1, 1);
        sum1 += __shfl_xor_sync(0xffffffffu, sum1, 2);
        l0 = l0 * al0 + sum0;  m0 = mn0;
        l1 = l1 * al1 + sum1;  m1 = mn1;
#pragma unroll
        for (int nt = 0; nt < 8; ++nt) {
            oacc[nt][0] *= al0; oacc[nt][1] *= al0;
            oacc[nt][2] *= al1; oacc[nt][3] *= al1;
        }
        __syncwarp();

        // ---- O += P @ V ----
#pragma unroll
        for (int kc = 0; kc < 8; ++kc) {
            const int col = kc * 8 + t;
            uint32_t pa[4];
            pa[0] = __float_as_uint(Pw[g * 68 + col]);
            pa[1] = __float_as_uint(Pw[(g + 8) * 68 + col]);
            pa[2] = __float_as_uint(Pw[g * 68 + col + 4]);
            pa[3] = __float_as_uint(Pw[(g + 8) * 68 + col + 4]);
#pragma unroll
            for (int nt = 0; nt < 8; ++nt) {
                const uint2 vb2 = *(const uint2*)&Vf[((kc * 8 + nt) * 32 + lane) * 2];
                uint32_t bf[2] = {vb2.x, vb2.y};
                mma1688(oacc[nt], pa, bf);
            }
        }
        __syncthreads();   // all warps done with Kf/Vf before next stageKV
    }

    // ---- epilogue: normalize + head alpha, write ctx ----
    const float ah  = alphas[h];
    const float iv0 = ah / l0;
    const float iv1 = ah / l1;
    const int gr0 = qt * 64 + wid * 16 + g;
#pragma unroll
    for (int nt = 0; nt < 8; ++nt) {
        const int d0 = nt * 8 + 2 * t;
        *(float2*)(cb + (size_t)gr0 * Dd + d0) =
            make_float2(oacc[nt][0] * iv0, oacc[nt][1] * iv0);
        *(float2*)(cb + (size_t)(gr0 + 8) * Dd + d0) =
            make_float2(oacc[nt][2] * iv1, oacc[nt][3] * iv1);
    }
}

// ---------------------------------------------------------------------------
// out = LayerNorm(A + R) * g + b   (one block per row of 512, 256 threads)
// ---------------------------------------------------------------------------
__global__ void __launch_bounds__(256) add_ln_kernel(
    const float* __restrict__ A, const float* __restrict__ R,
    const float* __restrict__ g, const float* __restrict__ be,
    float* __restrict__ out)
{
    const int row = blockIdx.x;
    const int tid = threadIdx.x;
    const size_t base = (size_t)row * Dd;

    float v0 = A[base + tid]       + R[base + tid];
    float v1 = A[base + tid + 256] + R[base + tid + 256];

    __shared__ float red[8];
    __shared__ float mean_s, rstd_s;

    float s = v0 + v1;
#pragma unroll
    for (int off = 16; off > 0; off >>= 1) s += __shfl_xor_sync(0xffffffffu, s, off);
    if ((tid & 31) == 0) red[tid >> 5] = s;
    __syncthreads();
    if (tid == 0) {
        float tt = 0.f;
#pragma unroll
        for (int i = 0; i < 8; i++) tt += red[i];
        mean_s = tt * (1.0f / Dd);
    }
    __syncthreads();

    const float mean = mean_s;
    float d0 = v0 - mean, d1 = v1 - mean;
    float qq = d0 * d0 + d1 * d1;
#pragma unroll
    for (int off = 16; off > 0; off >>= 1) qq += __shfl_xor_sync(0xffffffffu, qq, off);
    if ((tid & 31) == 0) red[tid >> 5] = qq;
    __syncthreads();
    if (tid == 0) {
        float tt = 0.f;
#pragma unroll
        for (int i = 0; i < 8; i++) tt += red[i];
        rstd_s = rsqrtf(tt * (1.0f / Dd) + 1e-5f);
    }
    __syncthreads();

    const float rstd = rstd_s;
    out[base + tid]       = d0 * rstd * g[tid]       + be[tid];
    out[base + tid + 256] = d1 * rstd * g[tid + 256] + be[tid + 256];
}

// ---------------------------------------------------------------------------
extern "C" void kernel_launch(void* const* d_in, const int* in_sizes, int n_in,
                              void* d_out, int out_size)
{
    const float* x      = (const float*)d_in[0];
    // d_in[1] = attn_mask (equivalent to causal predicate; handled in-kernel)
    const float* Wq     = (const float*)d_in[2];
    const float* bq     = (const float*)d_in[3];
    const float* Wk     = (const float*)d_in[4];
    const float* bk     = (const float*)d_in[5];
    const float* Wv     = (const float*)d_in[6];
    const float* bv     = (const float*)d_in[7];
    const float* Wo     = (const float*)d_in[8];
    const float* bo     = (const float*)d_in[9];
    const float* alphas = (const float*)d_in[10];
    const float* ln1g   = (const float*)d_in[11];
    const float* ln1b   = (const float*)d_in[12];
    const float* W1     = (const float*)d_in[13];
    const float* b1     = (const float*)d_in[14];
    const float* W2     = (const float*)d_in[15];
    const float* b2     = (const float*)d_in[16];
    const float* ln2g   = (const float*)d_in[17];
    const float* ln2b   = (const float*)d_in[18];
    float* out = (float*)d_out;

    float *q, *k, *v, *ctx, *attn, *h, *ff1, *ff2;
    cudaGetSymbolAddress((void**)&q,    g_q);
    cudaGetSymbolAddress((void**)&k,    g_k);
    cudaGetSymbolAddress((void**)&v,    g_v);
    cudaGetSymbolAddress((void**)&ctx,  g_ctx);
    cudaGetSymbolAddress((void**)&attn, g_attn);
    cudaGetSymbolAddress((void**)&h,    g_h);
    cudaGetSymbolAddress((void**)&ff1,  g_ff1);
    cudaGetSymbolAddress((void**)&ff2,  g_ff2);

    const int gemm_smem = 16384 * 4;                 // 64 KB
    const int attn_smem = (12288 + 4352) * 4;        // 66,560 B
    cudaFuncSetAttribute(qkv_kernel,
                         cudaFuncAttributeMaxDynamicSharedMemorySize, gemm_smem);
    cudaFuncSetAttribute(tc_gemm_kernel<false>,
                         cudaFuncAttributeMaxDynamicSharedMemorySize, gemm_smem);
    cudaFuncSetAttribute(tc_gemm_kernel<true>,
                         cudaFuncAttributeMaxDynamicSharedMemorySize, gemm_smem);
    cudaFuncSetAttribute(attn_kernel,
                         cudaFuncAttributeMaxDynamicSharedMemorySize, attn_smem);

    const dim3 gQKV(Dd / 128, Mrows / 128, 3);  // (4, 32, 3)
    const dim3 gProj(Dd / 128, Mrows / 128);    // (4, 32)
    const dim3 gFF1(DFFf / 128, Mrows / 128);   // (16, 32)
    const dim3 gFF2(Dd / 128, Mrows / 128);     // (4, 32)

    // QKV projections — single merged launch
    qkv_kernel<<<gQKV, 256, gemm_smem>>>(x, Wq, bq, Wk, bk, Wv, bv, q, k, v);

    // tensor-core causal flash attention
    attn_kernel<<<dim3(Ss / 64, Bb * Hh), 128, attn_smem>>>(q, k, v, alphas, ctx);

    // output projection
    tc_gemm_kernel<false><<<gProj, 256, gemm_smem>>>(ctx, Wo, bo, attn, Dd, Dd);

    // residual + LN1 -> h
    add_ln_kernel<<<Mrows, 256>>>(x, attn, ln1g, ln1b, h);

    // FFN
    tc_gemm_kernel<true ><<<gFF1, 256, gemm_smem>>>(h,   W1, b1, ff1, DFFf, Dd);
    tc_gemm_kernel<false><<<gFF2, 256, gemm_smem>>>(ff1, W2, b2, ff2, Dd, DFFf);

    // residual + LN2 -> output
    add_ln_kernel<<<Mrows, 256>>>(h, ff2, ln2g, ln2b, out);
}

// round 13
// speedup vs baseline: 2.0990x; 2.0990x over previous
#include <cuda_runtime.h>
#include <cstdint>
#include <math.h>

// Problem constants
#define Bb   2
#define Ss   2048
#define Dd   512
#define Hh   8
#define DHh  64
#define DFFf 2048
#define Mrows (Bb * Ss)   // 4096

// ---------------- scratch (no allocation allowed) ----------------
__device__ float g_q[Mrows * Dd];
__device__ float g_k[Mrows * Dd];
__device__ float g_v[Mrows * Dd];
__device__ float g_ctx[Mrows * Dd];
__device__ float g_attn[Mrows * Dd];
__device__ float g_h[Mrows * Dd];
__device__ float g_ff1[(size_t)Mrows * DFFf];
__device__ float g_ff2[Mrows * Dd];

// =========================== helpers ====================================
__device__ __forceinline__ void mma1688(float* c, const uint32_t* a, const uint32_t* b) {
    asm volatile(
        "mma.sync.aligned.m16n8k8.row.col.f32.tf32.tf32.f32 "
        "{%0,%1,%2,%3}, {%4,%5,%6,%7}, {%8,%9}, {%0,%1,%2,%3};"
        : "+f"(c[0]), "+f"(c[1]), "+f"(c[2]), "+f"(c[3])
        : "r"(a[0]), "r"(a[1]), "r"(a[2]), "r"(a[3]),
          "r"(b[0]), "r"(b[1]));
}

// Padded block strides (u32 units) — staging STS banks spread.
#define ASTR 132   // GEMM A frag block stride (was 128)
#define BSTR 66    // GEMM B frag block stride (was 64)
#define KSTR 514   // attn K kc-block stride (was 512)
#define VNT  66    // attn V nt stride (was 64)
#define VKC  528   // attn V kc-block stride (8*66)

// Per-buffer sizes (u32): A = 32 blocks * ASTR, B = 64 blocks * BSTR
#define ABUF (32 * ASTR)   // 4224
#define BBUF (64 * BSTR)   // 4224

// ---------------------------------------------------------------------------
// tf32 mma.sync GEMM body: C[m,n] = sum_k A[m,k]*W[n,k] + bias[n]
// CTA tile 128x128x32, 256 thr = 8 warps (4x2), warp tile 32x64.
// Double-buffered padded frag-layout smem, interleaved single prefetch (R9).
// ---------------------------------------------------------------------------
template <bool RELU>
__device__ __forceinline__ void gemm_body(
    const float* __restrict__ A, const float* __restrict__ W,
    const float* __restrict__ bias, float* __restrict__ C,
    int N, int K)
{
    extern __shared__ uint32_t smg[];
    uint32_t* sAb[2] = { smg,            smg + ABUF };
    uint32_t* sBb[2] = { smg + 2 * ABUF, smg + 2 * ABUF + BBUF };

    const int tid  = threadIdx.x;
    const int wid  = tid >> 5;
    const int lane = tid & 31;
    const int wrow = wid >> 1;
    const int wcol = wid & 1;
    const int m0   = blockIdx.y * 128;
    const int n0   = blockIdx.x * 128;
    const int g    = lane >> 2;
    const int t    = lane & 3;

    float acc[2][8][4];
#pragma unroll
    for (int i = 0; i < 2; i++)
#pragma unroll
        for (int j = 0; j < 8; j++)
#pragma unroll
            for (int e = 0; e < 4; e++) acc[i][j][e] = 0.f;

    auto loadA = [&](float4* p, int k0) {
#pragma unroll
        for (int it = 0; it < 4; ++it) {
            const int f = tid + 256 * it;
            const int r = f >> 3, c4 = f & 7;
            p[it] = *(const float4*)(A + (size_t)(m0 + r) * K + k0 + c4 * 4);
        }
    };
    auto loadB = [&](float4* p, int k0) {
#pragma unroll
        for (int it = 0; it < 4; ++it) {
            const int f = tid + 256 * it;
            const int r = f >> 3, c4 = f & 7;
            p[it] = *(const float4*)(W + (size_t)(n0 + r) * K + k0 + c4 * 4);
        }
    };
    auto stageA = [&](uint32_t* buf, const float4* p) {
#pragma unroll
        for (int it = 0; it < 4; ++it) {
            const int f = tid + 256 * it;
            const int r = f >> 3, c4 = f & 7;
            const int mt = r >> 4, rr = r & 15;
            const int ga = rr & 7, rh = rr >> 3;
            const int ks = c4 >> 1, ch = c4 & 1;
            const int reg = rh + 2 * ch;
            uint32_t* dst = buf + (mt * 4 + ks) * ASTR + ga * 16 + reg;
            dst[0 * 4] = __float_as_uint(p[it].x);
            dst[1 * 4] = __float_as_uint(p[it].y);
            dst[2 * 4] = __float_as_uint(p[it].z);
            dst[3 * 4] = __float_as_uint(p[it].w);
        }
    };
    auto stageB = [&](uint32_t* buf, const float4* p) {
#pragma unroll
        for (int it = 0; it < 4; ++it) {
            const int f = tid + 256 * it;
            const int r = f >> 3, c4 = f & 7;
            const int nt = r >> 3, gb = r & 7;
            const int ks = c4 >> 1, reg = c4 & 1;
            uint32_t* dst = buf + (nt * 4 + ks) * BSTR + gb * 8 + reg;
            dst[0 * 2] = __float_as_uint(p[it].x);
            dst[1 * 2] = __float_as_uint(p[it].y);
            dst[2 * 2] = __float_as_uint(p[it].z);
            dst[3 * 2] = __float_as_uint(p[it].w);
        }
    };
    auto compute2 = [&](const uint32_t* bufA, const uint32_t* bufB, int ks0) {
#pragma unroll
        for (int ks = ks0; ks < ks0 + 2; ++ks) {
            uint32_t afr[2][4];
#pragma unroll
            for (int mt = 0; mt < 2; ++mt) {
                const uint4 va = *(const uint4*)
                    (bufA + ((wrow * 2 + mt) * 4 + ks) * ASTR + lane * 4);
                afr[mt][0] = va.x; afr[mt][1] = va.y;
                afr[mt][2] = va.z; afr[mt][3] = va.w;
            }
            uint32_t bfr[8][2];
#pragma unroll
            for (int nt = 0; nt < 8; ++nt) {
                const uint2 vb = *(const uint2*)
                    (bufB + ((wcol * 8 + nt) * 4 + ks) * BSTR + lane * 2);
                bfr[nt][0] = vb.x; bfr[nt][1] = vb.y;
            }
#pragma unroll
            for (int mt = 0; mt < 2; ++mt)
#pragma unroll
                for (int nt = 0; nt < 8; ++nt)
                    mma1688(acc[mt][nt], afr[mt], bfr[nt]);
        }
    };

    // ---- prologue: stage chunk 0 into buffer 0 ----
    {
        float4 p[4];
        loadA(p, 0); stageA(sAb[0], p);
        loadB(p, 0); stageB(sBb[0], p);
    }
    __syncthreads();

    const int nc = K >> 5;
    for (int c = 0; c < nc; ++c) {
        const int nb = c & 1, fb = nb ^ 1;
        const bool nxt = (c + 1 < nc);
        const int k1 = (c + 1) << 5;

        float4 pre[4];
        if (nxt) loadA(pre, k1);
        compute2(sAb[nb], sBb[nb], 0);
        if (nxt) stageA(sAb[fb], pre);
        if (nxt) loadB(pre, k1);
        compute2(sAb[nb], sBb[nb], 2);
        if (nxt) stageB(sBb[fb], pre);
        __syncthreads();
    }

    // ---- epilogue ----
#pragma unroll
    for (int mt = 0; mt < 2; ++mt) {
        const int rbase = m0 + wrow * 32 + mt * 16;
#pragma unroll
        for (int nt = 0; nt < 8; ++nt) {
            const int cbase = n0 + wcol * 64 + nt * 8 + t * 2;
            const float b0 = bias[cbase];
            const float b1 = bias[cbase + 1];
            float2 o0, o1;
            o0.x = acc[mt][nt][0] + b0;  o0.y = acc[mt][nt][1] + b1;
            o1.x = acc[mt][nt][2] + b0;  o1.y = acc[mt][nt][3] + b1;
            if (RELU) {
                o0.x = fmaxf(o0.x, 0.f); o0.y = fmaxf(o0.y, 0.f);
                o1.x = fmaxf(o1.x, 0.f); o1.y = fmaxf(o1.y, 0.f);
            }
            *(float2*)(C + (size_t)(rbase + g)     * N + cbase) = o0;
            *(float2*)(C + (size_t)(rbase + g + 8) * N + cbase) = o1;
        }
    }
}

template <bool RELU>
__global__ void __launch_bounds__(256)
tc_gemm_kernel(const float* __restrict__ A, const float* __restrict__ W,
               const float* __restrict__ bias, float* __restrict__ C,
               int N, int K)
{
    gemm_body<RELU>(A, W, bias, C, N, K);
}

// Merged QKV: grid.z selects {Wq,Wk,Wv}.
__global__ void __launch_bounds__(256)
qkv_kernel(const float* __restrict__ x,
           const float* __restrict__ Wq, const float* __restrict__ bq,
           const float* __restrict__ Wk, const float* __restrict__ bk,
           const float* __restrict__ Wv, const float* __restrict__ bv,
           float* __restrict__ q, float* __restrict__ k, float* __restrict__ v)
{
    const float* W; const float* bias; float* C;
    if (blockIdx.z == 0)      { W = Wq; bias = bq; C = q; }
    else if (blockIdx.z == 1) { W = Wk; bias = bk; C = k; }
    else                      { W = Wv; bias = bv; C = v; }
    gemm_body<false>(x, W, bias, C, Dd, Dd);
}

// ---------------------------------------------------------------------------
// Tensor-core causal flash attention (tf32 mma.sync), R9 structure with
// padded K/V frag strides to kill staging bank conflicts.
// grid = (S/64, B*H), 128 threads = 4 warps; warp owns 16 q rows.
// smem (u32): Qf 4096 | Kf 8*514=4112 | Vf 8*528=4224 | Psm 4352 = 16784
// ---------------------------------------------------------------------------
__global__ void __launch_bounds__(128, 3) attn_kernel(
    const float* __restrict__ q, const float* __restrict__ k,
    const float* __restrict__ v, const float* __restrict__ alphas,
    float* __restrict__ ctx)
{
    extern __shared__ uint32_t smu[];
    uint32_t* Qf  = smu;
    uint32_t* Kf  = smu + 4096;
    uint32_t* Vf  = smu + 4096 + 8 * KSTR;
    float*    Psm = (float*)(smu + 4096 + 8 * KSTR + 8 * VKC);

    const int qt = (gridDim.x - 1) - blockIdx.x;   // heavy first
    const int bh = blockIdx.y;
    const int b  = bh >> 3;
    const int h  = bh & 7;

    const size_t base = (size_t)b * Ss * Dd + (size_t)h * DHh;
    const float* qb = q + base;
    const float* kb = k + base;
    const float* vb = v + base;
    float* cb = ctx + base;

    const int tid  = threadIdx.x;
    const int wid  = tid >> 5;
    const int lane = tid & 31;
    const int g    = lane >> 2;
    const int t    = lane & 3;

    // ---- stage Q tile (64x64) into a-frag layout ----
#pragma unroll
    for (int it = 0; it < 8; ++it) {
        const int f  = tid + 128 * it;
        const int r  = f >> 4;           // 0..63
        const int c4 = f & 15;
        const float4 v4 = *(const float4*)(qb + (size_t)(qt * 64 + r) * Dd + c4 * 4);
        const int w   = r >> 4;
        const int rr  = r & 15;
        const int gg  = rr & 7;
        const int rh  = rr >> 3;
        const int kc  = c4 >> 1;
        const int reg = rh + 2 * (c4 & 1);
        uint32_t* dst = &Qf[(((w * 8 + kc) * 32) + gg * 4) * 4 + reg];
        dst[0 * 4] = __float_as_uint(v4.x);
        dst[1 * 4] = __float_as_uint(v4.y);
        dst[2 * 4] = __float_as_uint(v4.z);
        dst[3 * 4] = __float_as_uint(v4.w);
    }

    float oacc[8][4];
#pragma unroll
    for (int nt = 0; nt < 8; ++nt)
#pragma unroll
        for (int e = 0; e < 4; ++e) oacc[nt][e] = 0.f;
    float m0 = -1e30f, m1 = -1e30f, l0 = 0.f, l1 = 0.f;

    const int rloc0 = wid * 16 + g;
    const int nkt   = qt + 1;
    const float* Pw = Psm + wid * 1088;
    float* PwW      = Psm + wid * 1088;

    for (int kt = 0; kt < nkt; ++kt) {
        __syncthreads();   // prior frag reads done (covers Q stage on iter 0)

        // ---- stage K and V tiles (64x64 each) into padded b-frag layouts ----
#pragma unroll
        for (int it = 0; it < 8; ++it) {
            const int f  = tid + 128 * it;
            const int r  = f >> 4;        // 0..63
            const int c4 = f & 15;
            const size_t goff = (size_t)(kt * 64 + r) * Dd + c4 * 4;
            const float4 kv = *(const float4*)(kb + goff);
            {   // K: n-role = kpos (r), k-role = dim
                const int gg = r & 7, nt = r >> 3, kc = c4 >> 1, reg = c4 & 1;
                uint32_t* dst = &Kf[kc * KSTR + nt * 64 + gg * 8 + reg];
                dst[0] = __float_as_uint(kv.x); dst[2] = __float_as_uint(kv.y);
                dst[4] = __float_as_uint(kv.z); dst[6] = __float_as_uint(kv.w);
            }
            const float4 vv = *(const float4*)(vb + goff);
            {   // V: k-role = kpos (r), n-role = dim
                const int kc = r >> 3, tt = r & 7;
                const int tq = tt & 3, reg = tt >> 2;
                const int nt = c4 >> 1, gb = (c4 & 1) * 4;
                uint32_t* dst = &Vf[kc * VKC + nt * VNT + (gb * 4 + tq) * 2 + reg];
                dst[0]  = __float_as_uint(vv.x); dst[8]  = __float_as_uint(vv.y);
                dst[16] = __float_as_uint(vv.z); dst[24] = __float_as_uint(vv.w);
            }
        }
        __syncthreads();

        // ---- S = Q @ K^T ----
        float sacc[8][4];
#pragma unroll
        for (int nt = 0; nt < 8; ++nt)
#pragma unroll
            for (int e = 0; e < 4; ++e) sacc[nt][e] = 0.f;
#pragma unroll
        for (int kc = 0; kc < 8; ++kc) {
            const uint4 aq4 = *(const uint4*)&Qf[((wid * 8 + kc) * 32 + lane) * 4];
            uint32_t aq[4] = {aq4.x, aq4.y, aq4.z, aq4.w};
#pragma unroll
            for (int nt = 0; nt < 8; ++nt) {
                const uint2 kb2 = *(const uint2*)&Kf[kc * KSTR + nt * 64 + lane * 2];
                uint32_t bf[2] = {kb2.x, kb2.y};
                mma1688(sacc[nt], aq, bf);
            }
        }

        // ---- softmax (register/shuffle only) ----
        const bool diag = (kt == qt);
        const float scale = 0.125f;
        float rm0 = -1e30f, rm1 = -1e30f;
#pragma unroll
        for (int nt = 0; nt < 8; ++nt) {
            const int jc = nt * 8 + 2 * t;
            float s0 = sacc[nt][0] * scale;
            float s1 = sacc[nt][1] * scale;
            float s2 = sacc[nt][2] * scale;
            float s3 = sacc[nt][3] * scale;
            if (diag) {
                if (jc     > rloc0)     s0 = -1e30f;
                if (jc + 1 > rloc0)     s1 = -1e30f;
                if (jc     > rloc0 + 8) s2 = -1e30f;
                if (jc + 1 > rloc0 + 8) s3 = -1e30f;
            }
            sacc[nt][0] = s0; sacc[nt][1] = s1;
            sacc[nt][2] = s2; sacc[nt][3] = s3;
            rm0 = fmaxf(rm0, fmaxf(s0, s1));
            rm1 = fmaxf(rm1, fmaxf(s2, s3));
        }
        rm0 = fmaxf(rm0, __shfl_xor_sync(0xffffffffu, rm0, 1));
        rm0 = fmaxf(rm0, __shfl_xor_sync(0xffffffffu, rm0, 2));
        rm1 = fmaxf(rm1, __shfl_xor_sync(0xffffffffu, rm1, 1));
        rm1 = fmaxf(rm1, __shfl_xor_sync(0xffffffffu, rm1, 2));

        const float mn0 = fmaxf(m0, rm0);
        const float mn1 = fmaxf(m1, rm1);
        const float al0 = __expf(m0 - mn0);
        const float al1 = __expf(m1 - mn1);
        float sum0 = 0.f, sum1 = 0.f;
#pragma unroll
        for (int nt = 0; nt < 8; ++nt) {
            const int jc = nt * 8 + 2 * t;
            const float p0 = __expf(sacc[nt][0] - mn0);
            const float p1 = __expf(sacc[nt][1] - mn0);
            const float p2 = __expf(sacc[nt][2] - mn1);
            const float p3 = __expf(sacc[nt][3] - mn1);
            sum0 += p0 + p1;
            sum1 += p2 + p3;
            *(float2*)(PwW + g * 68 + jc)       = make_float2(p0, p1);
            *(float2*)(PwW + (g + 8) * 68 + jc) = make_float2(p2, p3);
        }
        sum0 += __shfl_xor_sync(0xffffffffu, sum0, 1);
        sum0 += __shfl_xor_sync(0xffffffffu, sum0, 2);
        sum1 += __shfl_xor_sync(0xffffffffu, sum1, 1);
        sum1 += __shfl_xor_sync(0xffffffffu, sum1, 2);
        l0 = l0 * al0 + sum0;  m0 = mn0;
        l1 = l1 * al1 + sum1;  m1 = mn1;
#pragma unroll
        for (int nt = 0; nt < 8; ++nt) {
            oacc[nt][0] *= al0; oacc[nt][1] *= al0;
            oacc[nt][2] *= al1; oacc[nt][3] *= al1;
        }
        __syncwarp();

        // ---- O += P @ V ----
#pragma unroll
        for (int kc = 0; kc < 8; ++kc) {
            const int col = kc * 8 + t;
            uint32_t pa[4];
            pa[0] = __float_as_uint(Pw[g * 68 + col]);
            pa[1] = __float_as_uint(Pw[(g + 8) * 68 + col]);
            pa[2] = __float_as_uint(Pw[g * 68 + col + 4]);
            pa[3] = __float_as_uint(Pw[(g + 8) * 68 + col + 4]);
#pragma unroll
            for (int nt = 0; nt < 8; ++nt) {
                const uint2 vb2 = *(const uint2*)&Vf[kc * VKC + nt * VNT + lane * 2];
                uint32_t bf[2] = {vb2.x, vb2.y};
                mma1688(oacc[nt], pa, bf);
            }
        }
        __syncwarp();   // P reads done before next iter's stores
    }

    // ---- epilogue: normalize + head alpha, write ctx ----
    const float ah  = alphas[h];
    const float iv0 = ah / l0;
    const float iv1 = ah / l1;
    const int gr0 = qt * 64 + wid * 16 + g;
#pragma unroll
    for (int nt = 0; nt < 8; ++nt) {
        const int d0 = nt * 8 + 2 * t;
        *(float2*)(cb + (size_t)gr0 * Dd + d0) =
            make_float2(oacc[nt][0] * iv0, oacc[nt][1] * iv0);
        *(float2*)(cb + (size_t)(gr0 + 8) * Dd + d0) =
            make_float2(oacc[nt][2] * iv1, oacc[nt][3] * iv1);
    }
}

// ---------------------------------------------------------------------------
// out = LayerNorm(A + R) * g + b   (one block per row of 512, 256 threads)
// ---------------------------------------------------------------------------
__global__ void __launch_bounds__(256) add_ln_kernel(
    const float* __restrict__ A, const float* __restrict__ R,
    const float* __restrict__ g, const float* __restrict__ be,
    float* __restrict__ out)
{
    const int row = blockIdx.x;
    const int tid = threadIdx.x;
    const size_t base = (size_t)row * Dd;

    float v0 = A[base + tid]       + R[base + tid];
    float v1 = A[base + tid + 256] + R[base + tid + 256];

    __shared__ float red[8];
    __shared__ float mean_s, rstd_s;

    float s = v0 + v1;
#pragma unroll
    for (int off = 16; off > 0; off >>= 1) s += __shfl_xor_sync(0xffffffffu, s, off);
    if ((tid & 31) == 0) red[tid >> 5] = s;
    __syncthreads();
    if (tid == 0) {
        float tt = 0.f;
#pragma unroll
        for (int i = 0; i < 8; i++) tt += red[i];
        mean_s = tt * (1.0f / Dd);
    }
    __syncthreads();

    const float mean = mean_s;
    float d0 = v0 - mean, d1 = v1 - mean;
    float qq = d0 * d0 + d1 * d1;
#pragma unroll
    for (int off = 16; off > 0; off >>= 1) qq += __shfl_xor_sync(0xffffffffu, qq, off);
    if ((tid & 31) == 0) red[tid >> 5] = qq;
    __syncthreads();
    if (tid == 0) {
        float tt = 0.f;
#pragma unroll
        for (int i = 0; i < 8; i++) tt += red[i];
        rstd_s = rsqrtf(tt * (1.0f / Dd) + 1e-5f);
    }
    __syncthreads();

    const float rstd = rstd_s;
    out[base + tid]       = d0 * rstd * g[tid]       + be[tid];
    out[base + tid + 256] = d1 * rstd * g[tid + 256] + be[tid + 256];
}

// ---------------------------------------------------------------------------
extern "C" void kernel_launch(void* const* d_in, const int* in_sizes, int n_in,
                              void* d_out, int out_size)
{
    const float* x      = (const float*)d_in[0];
    // d_in[1] = attn_mask (equivalent to causal predicate; handled in-kernel)
    const float* Wq     = (const float*)d_in[2];
    const float* bq     = (const float*)d_in[3];
    const float* Wk     = (const float*)d_in[4];
    const float* bk     = (const float*)d_in[5];
    const float* Wv     = (const float*)d_in[6];
    const float* bv     = (const float*)d_in[7];
    const float* Wo     = (const float*)d_in[8];
    const float* bo     = (const float*)d_in[9];
    const float* alphas = (const float*)d_in[10];
    const float* ln1g   = (const float*)d_in[11];
    const float* ln1b   = (const float*)d_in[12];
    const float* W1     = (const float*)d_in[13];
    const float* b1     = (const float*)d_in[14];
    const float* W2     = (const float*)d_in[15];
    const float* b2     = (const float*)d_in[16];
    const float* ln2g   = (const float*)d_in[17];
    const float* ln2b   = (const float*)d_in[18];
    float* out = (float*)d_out;

    float *q, *k, *v, *ctx, *attn, *h, *ff1, *ff2;
    cudaGetSymbolAddress((void**)&q,    g_q);
    cudaGetSymbolAddress((void**)&k,    g_k);
    cudaGetSymbolAddress((void**)&v,    g_v);
    cudaGetSymbolAddress((void**)&ctx,  g_ctx);
    cudaGetSymbolAddress((void**)&attn, g_attn);
    cudaGetSymbolAddress((void**)&h,    g_h);
    cudaGetSymbolAddress((void**)&ff1,  g_ff1);
    cudaGetSymbolAddress((void**)&ff2,  g_ff2);

    const int gemm_smem = (2 * ABUF + 2 * BBUF) * 4;              // 67,584 B
    const int attn_smem = (4096 + 8 * KSTR + 8 * VKC + 4352) * 4; // 67,136 B
    cudaFuncSetAttribute(qkv_kernel,
                         cudaFuncAttributeMaxDynamicSharedMemorySize, gemm_smem);
    cudaFuncSetAttribute(tc_gemm_kernel<false>,
                         cudaFuncAttributeMaxDynamicSharedMemorySize, gemm_smem);
    cudaFuncSetAttribute(tc_gemm_kernel<true>,
                         cudaFuncAttributeMaxDynamicSharedMemorySize, gemm_smem);
    cudaFuncSetAttribute(attn_kernel,
                         cudaFuncAttributeMaxDynamicSharedMemorySize, attn_smem);

    const dim3 gQKV(Dd / 128, Mrows / 128, 3);  // (4, 32, 3)
    const dim3 gProj(Dd / 128, Mrows / 128);    // (4, 32)
    const dim3 gFF1(DFFf / 128, Mrows / 128);   // (16, 32)
    const dim3 gFF2(Dd / 128, Mrows / 128);     // (4, 32)

    // QKV projections — single merged launch
    qkv_kernel<<<gQKV, 256, gemm_smem>>>(x, Wq, bq, Wk, bk, Wv, bv, q, k, v);

    // tensor-core causal flash attention
    attn_kernel<<<dim3(Ss / 64, Bb * Hh), 128, attn_smem>>>(q, k, v, alphas, ctx);

    // output projection
    tc_gemm_kernel<false><<<gProj, 256, gemm_smem>>>(ctx, Wo, bo, attn, Dd, Dd);

    // residual + LN1 -> h
    add_ln_kernel<<<Mrows, 256>>>(x, attn, ln1g, ln1b, h);

    // FFN
    tc_gemm_kernel<true ><<<gFF1, 256, gemm_smem>>>(h,   W1, b1, ff1, DFFf, Dd);
    tc_gemm_kernel<false><<<gFF2, 256, gemm_smem>>>(ff1, W2, b2, ff2, Dd, DFFf);

    // residual + LN2 -> output
    add_ln_kernel<<<Mrows, 256>>>(h, ff2, ln2g, ln2b, out);
}